// round 12
// baseline (speedup 1.0000x reference)
#include <cuda_runtime.h>

// Shapes (fixed):
//   x:   (176, 64, 56, 56) f32
//   y:   (176, 128, 28, 28) f32
//   out: (176, 192, 56, 56) f32 = concat(x, nearest_upsample2x(y)) on channels
//
// FINAL kernel. Fused single-launch, phase-segregated block order (measured
// faster than both fine and chunked interleaving). Converged at the HBM
// roofline: 636 MB total traffic (theoretic floor — every byte touched once)
// in ~88.7us => ~7.2 TB/s effective, ~97% of the B300 practical LTS ceiling.
namespace cfg {
constexpr int B  = 176;
constexpr int C1 = 64;
constexpr int C2 = 128;
constexpr int H1 = 56;
constexpr int W1 = 56;
constexpr int H2 = 28;

constexpr int HW1_F4       = H1 * W1 / 4;        // 784 out float4 per plane
constexpr int X_F4_PER_B   = C1 * HW1_F4;        // 50176 = 1024 * 49
constexpr int OUT_F4_PER_B = (C1 + C2) * HW1_F4; // 150528
constexpr int W1_F4        = W1 / 4;             // 14

constexpr int T = 256;

// x path: each block copies 1024 float4 (4 per thread, loads batched up front).
// A block never straddles a batch: 50176 / 1024 = 49 exactly.
constexpr int BLOCKS_PER_BATCH_X = X_F4_PER_B / (4 * T);  // 49
constexpr int XBLK = B * BLOCKS_PER_BATCH_X;              // 8624

// y path: each thread handles 2 y float2s (block covers 512), loads batched.
constexpr int N_YUP = B * C2 * H2 * W1_F4;                // 8,830,976 float2
constexpr int YBLK  = N_YUP / (2 * T);                    // 17,248 (exact)
}

__device__ __forceinline__ int yup_out_index(int i) {
    // i = ((b*C2 + c)*H2 + h2)*14 + w4
    int w4 = i % cfg::W1_F4;
    int t  = i / cfg::W1_F4;                // (b*C2+c)*H2 + h2
    int h2 = t % cfg::H2;
    int bc = t / cfg::H2;                   // b*C2 + c
    int c  = bc % cfg::C2;
    int b  = bc / cfg::C2;
    return b * cfg::OUT_F4_PER_B
         + (cfg::C1 + c) * cfg::HW1_F4
         + (2 * h2) * cfg::W1_F4 + w4;
}

__global__ void __launch_bounds__(cfg::T) fused_concat_upsample(
    const float4* __restrict__ x,
    const float2* __restrict__ y2,
    float4* __restrict__ out)
{
    int bid = blockIdx.x;
    if (bid < cfg::XBLK) {
        // ---- x copy: out channels [0,64) ----
        int b  = bid / cfg::BLOCKS_PER_BATCH_X;
        int i0 = bid * (4 * cfg::T) + threadIdx.x;
        // 4 independent, fully-coalesced loads batched up front (MLP=4)
        float4 v0 = x[i0];
        float4 v1 = x[i0 + 1 * cfg::T];
        float4 v2 = x[i0 + 2 * cfg::T];
        float4 v3 = x[i0 + 3 * cfg::T];
        int o0 = b * cfg::OUT_F4_PER_B + (i0 - b * cfg::X_F4_PER_B);
        __stcs(&out[o0],              v0);   // write-once: evict-first
        __stcs(&out[o0 + 1 * cfg::T], v1);
        __stcs(&out[o0 + 2 * cfg::T], v2);
        __stcs(&out[o0 + 3 * cfg::T], v3);
    } else {
        // ---- y nearest-2x upsample: out channels [64,192) ----
        int i0 = (bid - cfg::XBLK) * (2 * cfg::T) + threadIdx.x;
        int i1 = i0 + cfg::T;
        // i = ((b*C2 + c)*H2 + h2)*14 + w4  — exactly the y2 index.
        // two independent loads batched up front (MLP=2 on the read stream)
        float2 va = y2[i0];
        float2 vb = y2[i1];

        int oa = yup_out_index(i0);
        int ob = yup_out_index(i1);

        float4 a;
        a.x = va.x; a.y = va.x; a.z = va.y; a.w = va.y;
        float4 b;
        b.x = vb.x; b.y = vb.x; b.z = vb.y; b.w = vb.y;

        __stcs(&out[oa],              a);   // row 2*h2   (warp-contiguous STG.128)
        __stcs(&out[oa + cfg::W1_F4], a);   // row 2*h2+1
        __stcs(&out[ob],              b);
        __stcs(&out[ob + cfg::W1_F4], b);
    }
}

extern "C" void kernel_launch(void* const* d_in, const int* in_sizes, int n_in,
                              void* d_out, int out_size) {
    const float4* x  = (const float4*)d_in[0];
    const float2* y2 = (const float2*)d_in[1];
    float4* out = (float4*)d_out;

    fused_concat_upsample<<<cfg::XBLK + cfg::YBLK, cfg::T>>>(x, y2, out);
}

// round 13
// speedup vs baseline: 1.0047x; 1.0047x over previous
#include <cuda_runtime.h>

// Shapes (fixed):
//   x:   (176, 64, 56, 56) f32
//   y:   (176, 128, 28, 28) f32
//   out: (176, 192, 56, 56) f32 = concat(x, nearest_upsample2x(y)) on channels
//
// Fused single-launch, phase-segregated block order. At the HBM roofline:
// 636 MB total traffic (theoretic floor) in ~89us. This round: streaming
// (evict-first) hints on LOADS as well — the last untested cache knob.
namespace cfg {
constexpr int B  = 176;
constexpr int C1 = 64;
constexpr int C2 = 128;
constexpr int H1 = 56;
constexpr int W1 = 56;
constexpr int H2 = 28;

constexpr int HW1_F4       = H1 * W1 / 4;        // 784 out float4 per plane
constexpr int X_F4_PER_B   = C1 * HW1_F4;        // 50176 = 1024 * 49
constexpr int OUT_F4_PER_B = (C1 + C2) * HW1_F4; // 150528
constexpr int W1_F4        = W1 / 4;             // 14

constexpr int T = 256;

// x path: each block copies 1024 float4 (4 per thread, loads batched up front).
// A block never straddles a batch: 50176 / 1024 = 49 exactly.
constexpr int BLOCKS_PER_BATCH_X = X_F4_PER_B / (4 * T);  // 49
constexpr int XBLK = B * BLOCKS_PER_BATCH_X;              // 8624

// y path: each thread handles 2 y float2s (block covers 512), loads batched.
constexpr int N_YUP = B * C2 * H2 * W1_F4;                // 8,830,976 float2
constexpr int YBLK  = N_YUP / (2 * T);                    // 17,248 (exact)
}

__device__ __forceinline__ int yup_out_index(int i) {
    // i = ((b*C2 + c)*H2 + h2)*14 + w4
    int w4 = i % cfg::W1_F4;
    int t  = i / cfg::W1_F4;                // (b*C2+c)*H2 + h2
    int h2 = t % cfg::H2;
    int bc = t / cfg::H2;                   // b*C2 + c
    int c  = bc % cfg::C2;
    int b  = bc / cfg::C2;
    return b * cfg::OUT_F4_PER_B
         + (cfg::C1 + c) * cfg::HW1_F4
         + (2 * h2) * cfg::W1_F4 + w4;
}

__global__ void __launch_bounds__(cfg::T) fused_concat_upsample(
    const float4* __restrict__ x,
    const float2* __restrict__ y2,
    float4* __restrict__ out)
{
    int bid = blockIdx.x;
    if (bid < cfg::XBLK) {
        // ---- x copy: out channels [0,64) ----
        int b  = bid / cfg::BLOCKS_PER_BATCH_X;
        int i0 = bid * (4 * cfg::T) + threadIdx.x;
        // 4 independent, fully-coalesced streaming loads batched up front
        float4 v0 = __ldcs(&x[i0]);
        float4 v1 = __ldcs(&x[i0 + 1 * cfg::T]);
        float4 v2 = __ldcs(&x[i0 + 2 * cfg::T]);
        float4 v3 = __ldcs(&x[i0 + 3 * cfg::T]);
        int o0 = b * cfg::OUT_F4_PER_B + (i0 - b * cfg::X_F4_PER_B);
        __stcs(&out[o0],              v0);   // write-once: evict-first
        __stcs(&out[o0 + 1 * cfg::T], v1);
        __stcs(&out[o0 + 2 * cfg::T], v2);
        __stcs(&out[o0 + 3 * cfg::T], v3);
    } else {
        // ---- y nearest-2x upsample: out channels [64,192) ----
        int i0 = (bid - cfg::XBLK) * (2 * cfg::T) + threadIdx.x;
        int i1 = i0 + cfg::T;
        // i = ((b*C2 + c)*H2 + h2)*14 + w4  — exactly the y2 index.
        float2 va = __ldcs(&y2[i0]);
        float2 vb = __ldcs(&y2[i1]);

        int oa = yup_out_index(i0);
        int ob = yup_out_index(i1);

        float4 a;
        a.x = va.x; a.y = va.x; a.z = va.y; a.w = va.y;
        float4 b;
        b.x = vb.x; b.y = vb.x; b.z = vb.y; b.w = vb.y;

        __stcs(&out[oa],              a);   // row 2*h2   (warp-contiguous STG.128)
        __stcs(&out[oa + cfg::W1_F4], a);   // row 2*h2+1
        __stcs(&out[ob],              b);
        __stcs(&out[ob + cfg::W1_F4], b);
    }
}

extern "C" void kernel_launch(void* const* d_in, const int* in_sizes, int n_in,
                              void* d_out, int out_size) {
    const float4* x  = (const float4*)d_in[0];
    const float2* y2 = (const float2*)d_in[1];
    float4* out = (float4*)d_out;

    fused_concat_upsample<<<cfg::XBLK + cfg::YBLK, cfg::T>>>(x, y2, out);
}